// round 4
// baseline (speedup 1.0000x reference)
#include <cuda_runtime.h>
#include <stdint.h>

#define N_NODES_MAX 100000
#define N_EDGES_MAX 400000
#define DIM 128
#define AS_LD 132
#define WS_LD 136
#define SMEM_BYTES ((64 * AS_LD + 128 * WS_LD) * 4)

// ---------------- scratch (device globals; no allocation allowed) ----------
__device__ int   g_deg[N_NODES_MAX];
__device__ int   g_off[N_NODES_MAX];
__device__ int   g_cur[N_NODES_MAX];
__device__ int   g_srcs[N_EDGES_MAX];
__device__ int   g_bsum[160];
__device__ float g_h[(size_t)N_NODES_MAX * DIM];
__device__ float g_sum[DIM];
__device__ float g_sumsq[DIM];
__device__ float g_scale[DIM];
__device__ float g_shift[DIM];
__device__ unsigned g_w1t[128 * WS_LD];
__device__ unsigned g_w2t[128 * WS_LD];

__device__ __forceinline__ unsigned f2tf32(float f) {
    unsigned u;
    asm("cvt.rna.tf32.f32 %0, %1;" : "=r"(u) : "f"(f));
    return u;
}

__device__ __forceinline__ void mma_tf32(float c[4], unsigned a0, unsigned a1,
                                         unsigned a2, unsigned a3,
                                         unsigned b0, unsigned b1) {
    asm volatile(
        "mma.sync.aligned.m16n8k8.row.col.f32.tf32.tf32.f32 "
        "{%0,%1,%2,%3}, {%4,%5,%6,%7}, {%8,%9}, {%0,%1,%2,%3};"
        : "+f"(c[0]), "+f"(c[1]), "+f"(c[2]), "+f"(c[3])
        : "r"(a0), "r"(a1), "r"(a2), "r"(a3), "r"(b0), "r"(b1));
}

// K0: zero degree counters & BN accumulators; build transposed tf32 weights
__global__ void k_prep(const float* __restrict__ w1, const float* __restrict__ w2, int n) {
    int i = blockIdx.x * blockDim.x + threadIdx.x;
    if (i < n) g_deg[i] = 0;
    if (i < DIM) { g_sum[i] = 0.f; g_sumsq[i] = 0.f; }
    if (i < 128 * WS_LD) {
        int k = i / WS_LD, c = i % WS_LD;
        unsigned v1 = 0, v2 = 0;
        if (c < 128) { v1 = f2tf32(w1[c * 128 + k]); v2 = f2tf32(w2[c * 128 + k]); }
        g_w1t[i] = v1;
        g_w2t[i] = v2;
    }
}

// K1: histogram of in-degrees (edge_index is int32: [2][E] row-major)
__global__ void k_hist(const int* __restrict__ ei, int e, int n) {
    int i = blockIdx.x * blockDim.x + threadIdx.x;
    if (i < e) {
        int d = ei[e + i];
        if ((unsigned)d < (unsigned)n) atomicAdd(&g_deg[d], 1);
    }
}

// K2: per-block exclusive scan (1024-wide Hillis-Steele)
__global__ void k_scan1(int n) {
    __shared__ int s[1024];
    int t = threadIdx.x, i = blockIdx.x * 1024 + t;
    int v = (i < n) ? g_deg[i] : 0;
    s[t] = v;
    __syncthreads();
    for (int o = 1; o < 1024; o <<= 1) {
        int x = (t >= o) ? s[t - o] : 0;
        __syncthreads();
        s[t] += x;
        __syncthreads();
    }
    if (i < n) g_off[i] = s[t] - v;
    if (t == 1023) g_bsum[blockIdx.x] = s[t];
}

// K3: scan the (<=160) block totals
__global__ void k_scan2(int nb) {
    if (threadIdx.x == 0) {
        int acc = 0;
        for (int b = 0; b < nb; b++) { int v = g_bsum[b]; g_bsum[b] = acc; acc += v; }
    }
}

// K4: add block offsets; init cursors
__global__ void k_scan3(int n) {
    int i = blockIdx.x * blockDim.x + threadIdx.x;
    if (i < n) {
        int o = g_off[i] + g_bsum[i >> 10];
        g_off[i] = o;
        g_cur[i] = o;
    }
}

// K5: scatter src indices into CSR
__global__ void k_scatter(const int* __restrict__ ei, int e, int n) {
    int i = blockIdx.x * blockDim.x + threadIdx.x;
    if (i < e) {
        int d = ei[e + i];
        int s = ei[i];
        if ((unsigned)d < (unsigned)n && (unsigned)s < (unsigned)n) {
            int p = atomicAdd(&g_cur[d], 1);
            if ((unsigned)p < (unsigned)N_EDGES_MAX) g_srcs[p] = s;
        }
    }
}

// K6: per-node gather-sum: h = x + sum(neighbors)  (1 warp / node, float4)
__global__ void k_agg(const float* __restrict__ x, int n) {
    int warp = (blockIdx.x * blockDim.x + threadIdx.x) >> 5;
    int lane = threadIdx.x & 31;
    if (warp >= n) return;
    float4 acc = ((const float4*)(x + (size_t)warp * DIM))[lane];
    int e = g_off[warp];
    int end = e + g_deg[warp];
    for (; e + 4 <= end; e += 4) {
        int s0 = g_srcs[e], s1 = g_srcs[e + 1], s2 = g_srcs[e + 2], s3 = g_srcs[e + 3];
        float4 v0 = ((const float4*)(x + (size_t)s0 * DIM))[lane];
        float4 v1 = ((const float4*)(x + (size_t)s1 * DIM))[lane];
        float4 v2 = ((const float4*)(x + (size_t)s2 * DIM))[lane];
        float4 v3 = ((const float4*)(x + (size_t)s3 * DIM))[lane];
        acc.x += v0.x + v1.x + v2.x + v3.x;
        acc.y += v0.y + v1.y + v2.y + v3.y;
        acc.z += v0.z + v1.z + v2.z + v3.z;
        acc.w += v0.w + v1.w + v2.w + v3.w;
    }
    for (; e < end; e++) {
        float4 v = ((const float4*)(x + (size_t)g_srcs[e] * DIM))[lane];
        acc.x += v.x; acc.y += v.y; acc.z += v.z; acc.w += v.w;
    }
    ((float4*)(g_h + (size_t)warp * DIM))[lane] = acc;
}

// K7: fused MLP: relu(relu(h@W1^T+b1)@W2^T+b2) -> out, + BN column partial sums
__global__ void __launch_bounds__(256, 2)
k_gemm(const float* __restrict__ b1, const float* __restrict__ b2,
       float* __restrict__ out, int M) {
    extern __shared__ unsigned sm[];
    unsigned* As = sm;                 // 64 x AS_LD (tf32 bits / fp32 bits)
    unsigned* Ws = sm + 64 * AS_LD;    // 128 x WS_LD (tf32 bits, [k][n])
    float* Asf = (float*)As;

    const int t = threadIdx.x;
    const int lane = t & 31, wid = t >> 5;
    const int g = lane >> 2, tig = lane & 3;
    const int mi = wid & 1;   // row half of tile (32 rows)
    const int nq = wid >> 1;  // col quarter (32 cols)
    const int row0 = blockIdx.x * 64;

    // stage A tile (tf32-rounded)
    for (int i = t; i < 64 * 32; i += 256) {
        int r = i >> 5, c4 = i & 31;
        float4 v = make_float4(0.f, 0.f, 0.f, 0.f);
        if (row0 + r < M) v = *(const float4*)(g_h + (size_t)(row0 + r) * DIM + c4 * 4);
        unsigned* p = As + r * AS_LD + c4 * 4;
        p[0] = f2tf32(v.x); p[1] = f2tf32(v.y); p[2] = f2tf32(v.z); p[3] = f2tf32(v.w);
    }
    for (int i = t; i < 128 * WS_LD; i += 256) Ws[i] = g_w1t[i];
    __syncthreads();

    float c[2][4][4];

    // ---------- layer 1 ----------
#pragma unroll
    for (int m = 0; m < 2; m++)
#pragma unroll
        for (int nt = 0; nt < 4; nt++)
#pragma unroll
            for (int j = 0; j < 4; j++) c[m][nt][j] = 0.f;

#pragma unroll 4
    for (int ks = 0; ks < 16; ks++) {
        int k0 = ks * 8;
        unsigned a[2][4];
#pragma unroll
        for (int m = 0; m < 2; m++) {
            int rb = mi * 32 + m * 16;
            a[m][0] = As[(rb + g) * AS_LD + k0 + tig];
            a[m][1] = As[(rb + g + 8) * AS_LD + k0 + tig];
            a[m][2] = As[(rb + g) * AS_LD + k0 + tig + 4];
            a[m][3] = As[(rb + g + 8) * AS_LD + k0 + tig + 4];
        }
#pragma unroll
        for (int nt = 0; nt < 4; nt++) {
            unsigned bb0 = Ws[(k0 + tig) * WS_LD + nq * 32 + nt * 8 + g];
            unsigned bb1 = Ws[(k0 + tig + 4) * WS_LD + nq * 32 + nt * 8 + g];
            mma_tf32(c[0][nt], a[0][0], a[0][1], a[0][2], a[0][3], bb0, bb1);
            mma_tf32(c[1][nt], a[1][0], a[1][1], a[1][2], a[1][3], bb0, bb1);
        }
    }
    __syncthreads();

    // epilogue 1: relu(c + b1) -> As (tf32); reload Ws = W2
#pragma unroll
    for (int m = 0; m < 2; m++)
#pragma unroll
        for (int nt = 0; nt < 4; nt++) {
            int cc = nq * 32 + nt * 8 + tig * 2;
            float bb0 = __ldg(b1 + cc), bb1v = __ldg(b1 + cc + 1);
            int r0l = mi * 32 + m * 16 + g;
            float v00 = fmaxf(c[m][nt][0] + bb0, 0.f);
            float v01 = fmaxf(c[m][nt][1] + bb1v, 0.f);
            float v10 = fmaxf(c[m][nt][2] + bb0, 0.f);
            float v11 = fmaxf(c[m][nt][3] + bb1v, 0.f);
            *(uint2*)(As + r0l * AS_LD + cc) = make_uint2(f2tf32(v00), f2tf32(v01));
            *(uint2*)(As + (r0l + 8) * AS_LD + cc) = make_uint2(f2tf32(v10), f2tf32(v11));
        }
    for (int i = t; i < 128 * WS_LD; i += 256) Ws[i] = g_w2t[i];
    __syncthreads();

    // ---------- layer 2 ----------
#pragma unroll
    for (int m = 0; m < 2; m++)
#pragma unroll
        for (int nt = 0; nt < 4; nt++)
#pragma unroll
            for (int j = 0; j < 4; j++) c[m][nt][j] = 0.f;

#pragma unroll 4
    for (int ks = 0; ks < 16; ks++) {
        int k0 = ks * 8;
        unsigned a[2][4];
#pragma unroll
        for (int m = 0; m < 2; m++) {
            int rb = mi * 32 + m * 16;
            a[m][0] = As[(rb + g) * AS_LD + k0 + tig];
            a[m][1] = As[(rb + g + 8) * AS_LD + k0 + tig];
            a[m][2] = As[(rb + g) * AS_LD + k0 + tig + 4];
            a[m][3] = As[(rb + g + 8) * AS_LD + k0 + tig + 4];
        }
#pragma unroll
        for (int nt = 0; nt < 4; nt++) {
            unsigned bb0 = Ws[(k0 + tig) * WS_LD + nq * 32 + nt * 8 + g];
            unsigned bb1 = Ws[(k0 + tig + 4) * WS_LD + nq * 32 + nt * 8 + g];
            mma_tf32(c[0][nt], a[0][0], a[0][1], a[0][2], a[0][3], bb0, bb1);
            mma_tf32(c[1][nt], a[1][0], a[1][1], a[1][2], a[1][3], bb0, bb1);
        }
    }
    __syncthreads();  // all reads of h1 tile complete

    // epilogue 2: relu(c + b2) -> As as raw fp32
#pragma unroll
    for (int m = 0; m < 2; m++)
#pragma unroll
        for (int nt = 0; nt < 4; nt++) {
            int cc = nq * 32 + nt * 8 + tig * 2;
            float bb0 = __ldg(b2 + cc), bb1v = __ldg(b2 + cc + 1);
            int r0l = mi * 32 + m * 16 + g;
            float v00 = fmaxf(c[m][nt][0] + bb0, 0.f);
            float v01 = fmaxf(c[m][nt][1] + bb1v, 0.f);
            float v10 = fmaxf(c[m][nt][2] + bb0, 0.f);
            float v11 = fmaxf(c[m][nt][3] + bb1v, 0.f);
            *(float2*)(Asf + r0l * AS_LD + cc) = make_float2(v00, v01);
            *(float2*)(Asf + (r0l + 8) * AS_LD + cc) = make_float2(v10, v11);
        }
    __syncthreads();

    // coalesced store of h2 (pre-BN) into out
    for (int i = t; i < 64 * 32; i += 256) {
        int r = i >> 5, c4 = i & 31;
        if (row0 + r < M)
            *(float4*)(out + (size_t)(row0 + r) * DIM + c4 * 4) =
                *(const float4*)(Asf + r * AS_LD + c4 * 4);
    }

    // BN column partial sums
    int col = t & 127, half = t >> 7;
    float s = 0.f, ss = 0.f;
    for (int r = half * 32; r < half * 32 + 32; r++) {
        if (row0 + r < M) {
            float v = Asf[r * AS_LD + col];
            s += v;
            ss += v * v;
        }
    }
    atomicAdd(&g_sum[col], s);
    atomicAdd(&g_sumsq[col], ss);
}

// K8: finalize BN stats -> scale/shift
__global__ void k_bnstats(const float* __restrict__ gamma, const float* __restrict__ beta, int n) {
    int c = threadIdx.x;
    if (c < DIM) {
        float inv = 1.f / (float)n;
        float mean = g_sum[c] * inv;
        float var = fmaxf(g_sumsq[c] * inv - mean * mean, 0.f);
        float sc = gamma[c] * rsqrtf(var + 1e-5f);
        g_scale[c] = sc;
        g_shift[c] = beta[c] - mean * sc;
    }
}

// K9: in-place BN apply (float4)
__global__ void k_apply(float* __restrict__ out, int total4) {
    int i = blockIdx.x * blockDim.x + threadIdx.x;
    if (i >= total4) return;
    int c4 = (i & 31) * 4;  // DIM/4 == 32
    float4 v = ((float4*)out)[i];
    float4 sc = *(const float4*)(g_scale + c4);
    float4 sh = *(const float4*)(g_shift + c4);
    v.x = v.x * sc.x + sh.x;
    v.y = v.y * sc.y + sh.y;
    v.z = v.z * sc.z + sh.z;
    v.w = v.w * sc.w + sh.w;
    ((float4*)out)[i] = v;
}

extern "C" void kernel_launch(void* const* d_in, const int* in_sizes, int n_in,
                              void* d_out, int out_size) {
    const float* feat = (const float*)d_in[0];
    const int* ei = (const int*)d_in[1];      // int32! (JAX x64 disabled downgrades int64)
    const float* w1 = (const float*)d_in[2];
    const float* b1 = (const float*)d_in[3];
    const float* w2 = (const float*)d_in[4];
    const float* b2 = (const float*)d_in[5];
    const float* gamma = (const float*)d_in[6];
    const float* beta = (const float*)d_in[7];
    float* out = (float*)d_out;

    int n = in_sizes[0] / DIM;   // 100000
    int e = in_sizes[1] / 2;     // 400000
    int nb1 = (n + 1023) / 1024; // 98

    cudaFuncSetAttribute(k_gemm, cudaFuncAttributeMaxDynamicSharedMemorySize, SMEM_BYTES);

    k_prep<<<(n + 255) / 256, 256>>>(w1, w2, n);
    k_hist<<<(e + 255) / 256, 256>>>(ei, e, n);
    k_scan1<<<nb1, 1024>>>(n);
    k_scan2<<<1, 32>>>(nb1);
    k_scan3<<<(n + 255) / 256, 256>>>(n);
    k_scatter<<<(e + 255) / 256, 256>>>(ei, e, n);
    k_agg<<<(n + 7) / 8, 256>>>(feat, n);   // 1 warp per node
    k_gemm<<<(n + 63) / 64, 256, SMEM_BYTES>>>(b1, b2, out, n);
    k_bnstats<<<1, 128>>>(gamma, beta, n);
    int total4 = n * DIM / 4;
    k_apply<<<(total4 + 255) / 256, 256>>>(out, total4);
}